// round 8
// baseline (speedup 1.0000x reference)
#include <cuda_runtime.h>

#define NB 8
#define NT 4095
#define NS 2048
#define ND 300
#define ND4 75            // ND / 4
#define PAD_IDX 1
#define NCHUNK 128
#define CLEN 16           // NS / NCHUNK
#define SUB 4             // rows per ty group (CLEN / 4)
#define NTILE 16          // pack tiles per batch (256 tokens each)
#define TILE 256

// ---- scratch (static __device__, no allocations) ----
__device__ __align__(16) int   g_leaves[NB * NS];
__device__ __align__(16) float g_prefix[(long)NB * (NS + 1) * ND];  // exclusive prefix
__device__ __align__(16) float g_csum[NB * NCHUNK * ND];
__device__ int g_cnt[NB * NTILE];

__device__ __forceinline__ float4 f4add(float4 a, float4 b) {
    a.x += b.x; a.y += b.y; a.z += b.z; a.w += b.w; return a;
}

// ---------------------------------------------------------------------------
// 1a) Count leaves per 256-token tile.  grid (NTILE, NB), block 256.
// ---------------------------------------------------------------------------
__global__ void count_kernel(const int* __restrict__ x, const int2* __restrict__ idx) {
    const int tile = blockIdx.x, b = blockIdx.y;
    const int tid = threadIdx.x;
    const int t = tile * TILE + tid;
    int flag = 0;
    if (t < NT) {
        int tok = x[b * NT + t];
        int2 lh = idx[b * NT + t];
        flag = (lh.x == lh.y && tok != PAD_IDX) ? 1 : 0;
    }
    unsigned m = __ballot_sync(0xffffffffu, flag);
    __shared__ int ws[8];
    if ((tid & 31) == 0) ws[tid >> 5] = __popc(m);
    __syncthreads();
    if (tid == 0) {
        int s = 0;
        #pragma unroll
        for (int i = 0; i < 8; i++) s += ws[i];
        g_cnt[b * NTILE + tile] = s;
    }
}

// ---------------------------------------------------------------------------
// 1b) Scatter leaves; last tile's block also PAD-fills the tail.
//     grid (NTILE, NB), block 256.
// ---------------------------------------------------------------------------
__global__ void scatter_kernel(const int* __restrict__ x, const int2* __restrict__ idx) {
    const int tile = blockIdx.x, b = blockIdx.y;
    const int tid = threadIdx.x;
    const int lane = tid & 31;
    const int w = tid >> 5;
    const int t = tile * TILE + tid;

    int flag = 0, tok = PAD_IDX;
    if (t < NT) {
        tok = x[b * NT + t];
        int2 lh = idx[b * NT + t];
        flag = (lh.x == lh.y && tok != PAD_IDX) ? 1 : 0;
    }
    unsigned m = __ballot_sync(0xffffffffu, flag);
    int within = __popc(m & ((1u << lane) - 1u));
    __shared__ int ws[8];
    if (lane == 0) ws[w] = __popc(m);
    __syncthreads();
    int woff = 0, bcnt = 0;
    #pragma unroll
    for (int i = 0; i < 8; i++) {
        int v = ws[i];
        if (i < w) woff += v;
        bcnt += v;
    }

    int base = 0;
    #pragma unroll
    for (int i = 0; i < NTILE; i++) if (i < tile) base += __ldg(&g_cnt[b * NTILE + i]);

    int pos = base + woff + within;
    if (flag && pos < NS) g_leaves[b * NS + pos] = tok;

    if (tile == NTILE - 1) {
        int total = base + bcnt;                 // same for all threads
        for (int p = total + tid; p < NS; p += TILE)
            g_leaves[b * NS + p] = PAD_IDX;      // W[PAD] row is zero
    }
}

// ---------------------------------------------------------------------------
// 2a) Chunk sums.  grid (NCHUNK, NB) = 1024 blocks, block (75, 4):
//     each ty sums SUB=4 rows, shared reduce, ty0 writes.
// ---------------------------------------------------------------------------
__global__ __launch_bounds__(300) void chunksum_kernel(const float4* __restrict__ W4) {
    const int c = blockIdx.x, b = blockIdx.y;
    const int j = threadIdx.x;                 // 0..74
    const int ty = threadIdx.y;                // 0..3

    const int4 l0 = *(const int4*)&g_leaves[b * NS + c * CLEN + ty * SUB];

    float4 v0 = __ldg(&W4[(long)l0.x * ND4 + j]);
    float4 v1 = __ldg(&W4[(long)l0.y * ND4 + j]);
    float4 v2 = __ldg(&W4[(long)l0.z * ND4 + j]);
    float4 v3 = __ldg(&W4[(long)l0.w * ND4 + j]);

    float4 s = f4add(f4add(v0, v1), f4add(v2, v3));

    __shared__ float4 s_sum[4][ND4];
    s_sum[ty][j] = s;
    __syncthreads();
    if (ty == 0) {
        float4 tot = f4add(f4add(s_sum[0][j], s_sum[1][j]),
                           f4add(s_sum[2][j], s_sum[3][j]));
        ((float4*)g_csum)[(b * NCHUNK + c) * ND4 + j] = tot;
    }
}

// ---------------------------------------------------------------------------
// 2b) Scan chunk sums in place -> exclusive chunk offsets.
//     One WARP per (b,d): lane holds chunks [4*lane, 4*lane+4), shfl scan.
// ---------------------------------------------------------------------------
__global__ void chunkscan_kernel() {
    int gw = (blockIdx.x * blockDim.x + threadIdx.x) >> 5;
    int lane = threadIdx.x & 31;
    if (gw >= NB * ND) return;
    int b = gw / ND, d = gw - b * ND;

    float* base = &g_csum[b * NCHUNK * ND + d];
    float v[4];
    float s = 0.f;
    #pragma unroll
    for (int r = 0; r < 4; r++) {
        v[r] = base[(4 * lane + r) * ND];
        s += v[r];
    }

    float incl = s;
    #pragma unroll
    for (int off = 1; off < 32; off <<= 1) {
        float n = __shfl_up_sync(0xffffffffu, incl, off);
        if (lane >= off) incl += n;
    }
    float acc = incl - s;
    #pragma unroll
    for (int r = 0; r < 4; r++) {
        base[(4 * lane + r) * ND] = acc;
        acc += v[r];
    }
}

// ---------------------------------------------------------------------------
// 2c) Exclusive prefix.  grid (NCHUNK, NB) = 1024 blocks, block (75, 4):
//     each ty gathers its 4 rows once, sub-sums exchanged via shared,
//     each ty writes its 4 prefix rows.  Last (c,ty) writes P[b][S].
// ---------------------------------------------------------------------------
__global__ __launch_bounds__(300) void prefix_kernel(const float4* __restrict__ W4) {
    const int c = blockIdx.x, b = blockIdx.y;
    const int j = threadIdx.x;                 // 0..74
    const int ty = threadIdx.y;                // 0..3
    const int row0 = c * CLEN + ty * SUB;

    const int4 l0 = *(const int4*)&g_leaves[b * NS + row0];

    float4 v0 = __ldg(&W4[(long)l0.x * ND4 + j]);
    float4 v1 = __ldg(&W4[(long)l0.y * ND4 + j]);
    float4 v2 = __ldg(&W4[(long)l0.z * ND4 + j]);
    float4 v3 = __ldg(&W4[(long)l0.w * ND4 + j]);

    float4 s = f4add(f4add(v0, v1), f4add(v2, v3));

    __shared__ float4 s_sum[4][ND4];
    s_sum[ty][j] = s;
    __syncthreads();

    float4 acc = ((const float4*)g_csum)[(b * NCHUNK + c) * ND4 + j];
    if (ty >= 1) acc = f4add(acc, s_sum[0][j]);
    if (ty >= 2) acc = f4add(acc, s_sum[1][j]);
    if (ty >= 3) acc = f4add(acc, s_sum[2][j]);

    float4* P = &((float4*)g_prefix)[((long)b * (NS + 1) + row0) * ND4 + j];
    P[0 * ND4] = acc; acc = f4add(acc, v0);
    P[1 * ND4] = acc; acc = f4add(acc, v1);
    P[2 * ND4] = acc; acc = f4add(acc, v2);
    P[3 * ND4] = acc; acc = f4add(acc, v3);
    if (c == NCHUNK - 1 && ty == 3) P[4 * ND4] = acc;   // P[b][S][:]
}

// ---------------------------------------------------------------------------
// 3) Query. Leaf rows (lo==hi): out = W[leaves[lo]] directly.
//    Internal rows: out = (P[hi+1] - P[lo]) / denom.
// ---------------------------------------------------------------------------
__global__ void out_kernel(const int2* __restrict__ idxp,
                           const float4* __restrict__ W4,
                           float4* __restrict__ out) {
    const float4* __restrict__ P4 = (const float4*)g_prefix;
    int i = blockIdx.x * blockDim.x + threadIdx.x;
    if (i >= NB * NT * ND4) return;
    int bt = i / ND4;
    int j = i - bt * ND4;
    int b = bt / NT;
    int2 lh = idxp[bt];
    if (lh.x == lh.y) {
        int leaf = g_leaves[b * NS + lh.x];
        out[i] = __ldg(&W4[(long)leaf * ND4 + j]);
        return;
    }
    int dn = lh.y - lh.x + 1;
    if (dn < 1) dn = 1;
    float inv = 1.0f / (float)dn;
    long base = (long)b * (NS + 1) * ND4;
    float4 a = __ldg(&P4[base + (long)(lh.y + 1) * ND4 + j]);
    float4 c = __ldg(&P4[base + (long)lh.x * ND4 + j]);
    float4 o;
    o.x = (a.x - c.x) * inv;
    o.y = (a.y - c.y) * inv;
    o.z = (a.z - c.z) * inv;
    o.w = (a.w - c.w) * inv;
    out[i] = o;
}

// ---------------------------------------------------------------------------
extern "C" void kernel_launch(void* const* d_in, const int* in_sizes, int n_in,
                              void* d_out, int out_size) {
    const int*  x   = (const int*)d_in[0];      // [B,T]   int32
    const int2* idx = (const int2*)d_in[1];     // [B,T,2] int32
    const float4* W4 = (const float4*)d_in[2];  // [V,D]   fp32
    float* out = (float*)d_out;                 // [B,T,D] fp32

    dim3 gpack(NTILE, NB);
    count_kernel<<<gpack, TILE>>>(x, idx);
    scatter_kernel<<<gpack, TILE>>>(x, idx);

    dim3 blk(75, 4);
    dim3 gfull(NCHUNK, NB);                     // 1024 blocks
    chunksum_kernel<<<gfull, blk>>>(W4);

    int nwarp = NB * ND;
    chunkscan_kernel<<<(nwarp * 32 + 255) / 256, 256>>>();

    prefix_kernel<<<gfull, blk>>>(W4);

    int n4 = NB * NT * ND4;
    out_kernel<<<(n4 + 255) / 256, 256>>>(idx, W4, (float4*)out);
}

// round 9
// speedup vs baseline: 1.1380x; 1.1380x over previous
#include <cuda_runtime.h>

#define NB 8
#define NT 4095
#define NS 2048
#define ND 300
#define ND4 75            // ND / 4
#define PAD_IDX 1
#define NCHUNK 128
#define CLEN 16           // NS / NCHUNK
#define SUB 4             // rows per ty group (CLEN / 4)
#define NTILE 16          // pack tiles per batch (256 tokens each)
#define TILE 256

// ---- scratch (static __device__, no allocations) ----
__device__ __align__(16) int   g_leaves[NB * NS];
__device__ __align__(16) float g_prefix[(long)NB * (NS + 1) * ND];  // exclusive prefix
__device__ __align__(16) float g_csum[NB * NCHUNK * ND];
__device__ int g_cnt[NB * NTILE];

__device__ __forceinline__ float4 f4add(float4 a, float4 b) {
    a.x += b.x; a.y += b.y; a.z += b.z; a.w += b.w; return a;
}

// ---------------------------------------------------------------------------
// 1a) Count leaves per 256-token tile.  grid (NTILE, NB), block 256.
// ---------------------------------------------------------------------------
__global__ void count_kernel(const int* __restrict__ x, const int2* __restrict__ idx) {
    const int tile = blockIdx.x, b = blockIdx.y;
    const int tid = threadIdx.x;
    const int t = tile * TILE + tid;
    int flag = 0;
    if (t < NT) {
        int tok = x[b * NT + t];
        int2 lh = idx[b * NT + t];
        flag = (lh.x == lh.y && tok != PAD_IDX) ? 1 : 0;
    }
    unsigned m = __ballot_sync(0xffffffffu, flag);
    __shared__ int ws[8];
    if ((tid & 31) == 0) ws[tid >> 5] = __popc(m);
    __syncthreads();
    if (tid == 0) {
        int s = 0;
        #pragma unroll
        for (int i = 0; i < 8; i++) s += ws[i];
        g_cnt[b * NTILE + tile] = s;
    }
}

// ---------------------------------------------------------------------------
// 1b) Scatter leaves; last tile's block also PAD-fills the tail.
//     grid (NTILE, NB), block 256.
// ---------------------------------------------------------------------------
__global__ void scatter_kernel(const int* __restrict__ x, const int2* __restrict__ idx) {
    const int tile = blockIdx.x, b = blockIdx.y;
    const int tid = threadIdx.x;
    const int lane = tid & 31;
    const int w = tid >> 5;
    const int t = tile * TILE + tid;

    int flag = 0, tok = PAD_IDX;
    if (t < NT) {
        tok = x[b * NT + t];
        int2 lh = idx[b * NT + t];
        flag = (lh.x == lh.y && tok != PAD_IDX) ? 1 : 0;
    }
    unsigned m = __ballot_sync(0xffffffffu, flag);
    int within = __popc(m & ((1u << lane) - 1u));
    __shared__ int ws[8];
    if (lane == 0) ws[w] = __popc(m);
    __syncthreads();
    int woff = 0, bcnt = 0;
    #pragma unroll
    for (int i = 0; i < 8; i++) {
        int v = ws[i];
        if (i < w) woff += v;
        bcnt += v;
    }

    int base = 0;
    #pragma unroll
    for (int i = 0; i < NTILE; i++) if (i < tile) base += __ldg(&g_cnt[b * NTILE + i]);

    int pos = base + woff + within;
    if (flag && pos < NS) g_leaves[b * NS + pos] = tok;

    if (tile == NTILE - 1) {
        int total = base + bcnt;                 // same for all threads
        for (int p = total + tid; p < NS; p += TILE)
            g_leaves[b * NS + p] = PAD_IDX;      // W[PAD] row is zero
    }
}

// ---------------------------------------------------------------------------
// 2a) Chunk sums.  grid (NCHUNK, NB) = 1024 blocks, block (75, 4):
//     each ty sums SUB=4 rows, shared reduce, ty0 writes.
// ---------------------------------------------------------------------------
__global__ __launch_bounds__(300) void chunksum_kernel(const float4* __restrict__ W4) {
    const int c = blockIdx.x, b = blockIdx.y;
    const int j = threadIdx.x;                 // 0..74
    const int ty = threadIdx.y;                // 0..3

    const int4 l0 = *(const int4*)&g_leaves[b * NS + c * CLEN + ty * SUB];

    float4 v0 = __ldg(&W4[(long)l0.x * ND4 + j]);
    float4 v1 = __ldg(&W4[(long)l0.y * ND4 + j]);
    float4 v2 = __ldg(&W4[(long)l0.z * ND4 + j]);
    float4 v3 = __ldg(&W4[(long)l0.w * ND4 + j]);

    float4 s = f4add(f4add(v0, v1), f4add(v2, v3));

    __shared__ float4 s_sum[4][ND4];
    s_sum[ty][j] = s;
    __syncthreads();
    if (ty == 0) {
        float4 tot = f4add(f4add(s_sum[0][j], s_sum[1][j]),
                           f4add(s_sum[2][j], s_sum[3][j]));
        ((float4*)g_csum)[(b * NCHUNK + c) * ND4 + j] = tot;
    }
}

// ---------------------------------------------------------------------------
// 2b) Coalesced block-cooperative chunk scan.  grid (5, NB), block (15, 32).
//     Thread (tx,ty) owns float4 lane j = bx*15+tx and chunks 4*ty..4*ty+3.
//     Loads are 240B-contiguous rows; cross-ty scan runs in shared memory.
// ---------------------------------------------------------------------------
__global__ __launch_bounds__(480) void chunkscan_kernel() {
    const int b  = blockIdx.y;
    const int tx = threadIdx.x;                 // 0..14
    const int ty = threadIdx.y;                 // 0..31
    const int j  = blockIdx.x * 15 + tx;        // 0..74

    float4* base = &((float4*)g_csum)[(long)b * NCHUNK * ND4 + j];

    float4 v0 = base[(4 * ty + 0) * ND4];
    float4 v1 = base[(4 * ty + 1) * ND4];
    float4 v2 = base[(4 * ty + 2) * ND4];
    float4 v3 = base[(4 * ty + 3) * ND4];
    const float4 s = f4add(f4add(v0, v1), f4add(v2, v3));

    __shared__ float4 sh[32][15];
    sh[ty][tx] = s;
    __syncthreads();

    float4 cur = s;
    #pragma unroll
    for (int off = 1; off < 32; off <<= 1) {
        float4 up = {0.f, 0.f, 0.f, 0.f};
        if (ty >= off) up = sh[ty - off][tx];
        __syncthreads();
        cur = f4add(cur, up);
        sh[ty][tx] = cur;
        __syncthreads();
    }

    // exclusive base for this thread's 4 chunks
    float4 acc = cur;
    acc.x -= s.x; acc.y -= s.y; acc.z -= s.z; acc.w -= s.w;

    base[(4 * ty + 0) * ND4] = acc; acc = f4add(acc, v0);
    base[(4 * ty + 1) * ND4] = acc; acc = f4add(acc, v1);
    base[(4 * ty + 2) * ND4] = acc; acc = f4add(acc, v2);
    base[(4 * ty + 3) * ND4] = acc;
}

// ---------------------------------------------------------------------------
// 2c) Exclusive prefix.  grid (NCHUNK, NB) = 1024 blocks, block (75, 4):
//     each ty gathers its 4 rows once, sub-sums exchanged via shared,
//     each ty writes its 4 prefix rows.  Last (c,ty) writes P[b][S].
// ---------------------------------------------------------------------------
__global__ __launch_bounds__(300) void prefix_kernel(const float4* __restrict__ W4) {
    const int c = blockIdx.x, b = blockIdx.y;
    const int j = threadIdx.x;                 // 0..74
    const int ty = threadIdx.y;                // 0..3
    const int row0 = c * CLEN + ty * SUB;

    const int4 l0 = *(const int4*)&g_leaves[b * NS + row0];

    float4 v0 = __ldg(&W4[(long)l0.x * ND4 + j]);
    float4 v1 = __ldg(&W4[(long)l0.y * ND4 + j]);
    float4 v2 = __ldg(&W4[(long)l0.z * ND4 + j]);
    float4 v3 = __ldg(&W4[(long)l0.w * ND4 + j]);

    float4 s = f4add(f4add(v0, v1), f4add(v2, v3));

    __shared__ float4 s_sum[4][ND4];
    s_sum[ty][j] = s;
    __syncthreads();

    float4 acc = ((const float4*)g_csum)[(b * NCHUNK + c) * ND4 + j];
    if (ty >= 1) acc = f4add(acc, s_sum[0][j]);
    if (ty >= 2) acc = f4add(acc, s_sum[1][j]);
    if (ty >= 3) acc = f4add(acc, s_sum[2][j]);

    float4* P = &((float4*)g_prefix)[((long)b * (NS + 1) + row0) * ND4 + j];
    P[0 * ND4] = acc; acc = f4add(acc, v0);
    P[1 * ND4] = acc; acc = f4add(acc, v1);
    P[2 * ND4] = acc; acc = f4add(acc, v2);
    P[3 * ND4] = acc; acc = f4add(acc, v3);
    if (c == NCHUNK - 1 && ty == 3) P[4 * ND4] = acc;   // P[b][S][:]
}

// ---------------------------------------------------------------------------
// 3) Query. Leaf rows (lo==hi): out = W[leaves[lo]] directly.
//    Internal rows: out = (P[hi+1] - P[lo]) / denom.
//    Output stores are streaming (write-once, never re-read).
// ---------------------------------------------------------------------------
__global__ void out_kernel(const int2* __restrict__ idxp,
                           const float4* __restrict__ W4,
                           float4* __restrict__ out) {
    const float4* __restrict__ P4 = (const float4*)g_prefix;
    int i = blockIdx.x * blockDim.x + threadIdx.x;
    if (i >= NB * NT * ND4) return;
    int bt = i / ND4;
    int j = i - bt * ND4;
    int b = bt / NT;
    int2 lh = idxp[bt];
    if (lh.x == lh.y) {
        int leaf = g_leaves[b * NS + lh.x];
        __stcs(&out[i], __ldg(&W4[(long)leaf * ND4 + j]));
        return;
    }
    int dn = lh.y - lh.x + 1;
    if (dn < 1) dn = 1;
    float inv = 1.0f / (float)dn;
    long base = (long)b * (NS + 1) * ND4;
    float4 a = __ldg(&P4[base + (long)(lh.y + 1) * ND4 + j]);
    float4 c = __ldg(&P4[base + (long)lh.x * ND4 + j]);
    float4 o;
    o.x = (a.x - c.x) * inv;
    o.y = (a.y - c.y) * inv;
    o.z = (a.z - c.z) * inv;
    o.w = (a.w - c.w) * inv;
    __stcs(&out[i], o);
}

// ---------------------------------------------------------------------------
extern "C" void kernel_launch(void* const* d_in, const int* in_sizes, int n_in,
                              void* d_out, int out_size) {
    const int*  x   = (const int*)d_in[0];      // [B,T]   int32
    const int2* idx = (const int2*)d_in[1];     // [B,T,2] int32
    const float4* W4 = (const float4*)d_in[2];  // [V,D]   fp32
    float* out = (float*)d_out;                 // [B,T,D] fp32

    dim3 gpack(NTILE, NB);
    count_kernel<<<gpack, TILE>>>(x, idx);
    scatter_kernel<<<gpack, TILE>>>(x, idx);

    dim3 blk(75, 4);
    dim3 gfull(NCHUNK, NB);                     // 1024 blocks
    chunksum_kernel<<<gfull, blk>>>(W4);

    dim3 gscan(5, NB);                          // 40 blocks
    dim3 bscan(15, 32);
    chunkscan_kernel<<<gscan, bscan>>>();

    prefix_kernel<<<gfull, blk>>>(W4);

    int n4 = NB * NT * ND4;
    out_kernel<<<(n4 + 255) / 256, 256>>>(idx, W4, (float4*)out);
}